// round 13
// baseline (speedup 1.0000x reference)
#include <cuda_runtime.h>

#define NHEADS 12
#define SEQ 197
#define CDIM 768
#define HD 64
#define QKV3 2304
#define BATCH 128
#define MROWS (BATCH * SEQ)   // 25216
#define SPAD 224
#define BH (BATCH * NHEADS)   // 1536

// Scratch (device globals: allocation-guard safe)
__device__ float g_qkv[(size_t)BATCH * SEQ * QKV3];
__device__ float g_attn[(size_t)BATCH * SEQ * CDIM];
__device__ float g_relbias[(size_t)NHEADS * SEQ * SPAD];
__device__ float g_bias[QKV3];

// ---------------------------------------------------------------------------
__global__ void build_bias_kernel(const float* __restrict__ qb,
                                  const float* __restrict__ vb) {
    int i = blockIdx.x * blockDim.x + threadIdx.x;
    if (i < QKV3) {
        g_bias[i] = (i < CDIM) ? qb[i] : ((i < 2 * CDIM) ? 0.0f : vb[i - 2 * CDIM]);
    }
}

__global__ void build_relbias_kernel(const float* __restrict__ table,
                                     const int* __restrict__ relidx) {
    int idx = blockIdx.x * blockDim.x + threadIdx.x;
    if (idx >= NHEADS * SEQ * SPAD) return;
    int h = idx / (SEQ * SPAD);
    int rem = idx - h * SEQ * SPAD;
    int i = rem / SPAD;
    int j = rem - i * SPAD;
    g_relbias[idx] = (j < SEQ) ? table[relidx[i * SEQ + j] * NHEADS + h] : 0.0f;
}

__device__ __forceinline__ float f2tf32(float x) {
    unsigned u;
    asm("cvt.rna.tf32.f32 %0, %1;" : "=r"(u) : "f"(x));
    return __uint_as_float(u);
}

// ---------------------------------------------------------------------------
// Packed-fragment TF32 GEMM, CTA tile 128x64, K-tile 32, 3 CTAs/SM target.
// 256 threads = 8 warps (4 M x 2 N), warp tile 32x32.
// A packed: float4 slot ((mblk*4+kblk)*8+g)*4 + (tig^kblk)      (4096 floats)
// B packed: float2 slot (((n>>3)*4+kb2)*8+(n&7))*4 + (e^kb2)    (2048 floats)
// ---------------------------------------------------------------------------
#define TA_F 4096
#define TB_F 2048
#define GSMEM_F (2 * (TA_F + TB_F))   // 12288 floats = 48 KB

__device__ __forceinline__ void g2_ldg(const float* __restrict__ Ab,
                                       const float* __restrict__ Bb,
                                       int K, int k0, int tid,
                                       float* ra, float* rb) {
#pragma unroll
    for (int i = 0; i < 2; i++) {
        int t = tid + i * 256;
        int khalf = t & 1, kblk = (t >> 1) & 3, g = (t >> 3) & 7, mblk = t >> 6;
        int r = mblk * 16 + g;
        int k = k0 + kblk * 8 + khalf * 4;
        float4 v0 = *(const float4*)(Ab + (size_t)r * K + k);
        float4 v1 = *(const float4*)(Ab + (size_t)(r + 8) * K + k);
        ra[i * 8 + 0] = v0.x; ra[i * 8 + 1] = v0.y; ra[i * 8 + 2] = v0.z; ra[i * 8 + 3] = v0.w;
        ra[i * 8 + 4] = v1.x; ra[i * 8 + 5] = v1.y; ra[i * 8 + 6] = v1.z; ra[i * 8 + 7] = v1.w;
    }
    // B: 256 tasks exactly (64 rows x 4 k-octets)
    int kb2 = tid & 3, n = tid >> 2;
    const float* bp = Bb + (size_t)n * K + k0 + kb2 * 8;
    float4 w0 = *(const float4*)(bp);
    float4 w1 = *(const float4*)(bp + 4);
    rb[0] = w0.x; rb[1] = w0.y; rb[2] = w0.z; rb[3] = w0.w;
    rb[4] = w1.x; rb[5] = w1.y; rb[6] = w1.z; rb[7] = w1.w;
}

__device__ __forceinline__ void g2_sts(float* __restrict__ Apk,
                                       float* __restrict__ Bpk,
                                       int tid, const float* ra, const float* rb) {
#pragma unroll
    for (int i = 0; i < 2; i++) {
        int t = tid + i * 256;
        int khalf = t & 1, kblk = (t >> 1) & 3, g = (t >> 3) & 7, mblk = t >> 6;
        int abase = ((mblk * 4 + kblk) * 8 + g) * 4;
#pragma unroll
        for (int e = 0; e < 4; e++) {
            int idx4 = abase + (e ^ kblk);
            *(float2*)&Apk[idx4 * 4 + 2 * khalf] =
                make_float2(f2tf32(ra[i * 8 + e]), f2tf32(ra[i * 8 + 4 + e]));
        }
    }
    int kb2 = tid & 3, n = tid >> 2;
    int bbase = (((n >> 3) * 4 + kb2) * 8 + (n & 7)) * 4;
#pragma unroll
    for (int e = 0; e < 4; e++) {
        int idx2 = bbase + (e ^ kb2);
        *(float2*)&Bpk[idx2 * 2] =
            make_float2(f2tf32(rb[e]), f2tf32(rb[4 + e]));
    }
}

__global__ __launch_bounds__(256, 3)
void gemm_tf32_bias(const float* __restrict__ A, const float* __restrict__ Bm,
                    const float* __restrict__ bias, float* __restrict__ C,
                    int M, int N, int K) {
    extern __shared__ float gsm[];
    float* Apk = gsm;                      // [2][4096]
    float* Bpk = gsm + 2 * TA_F;           // [2][2048]

    const int tid = threadIdx.x;
    const int lane = tid & 31;
    const int warp = tid >> 5;
    const int wm = warp >> 1, wn = warp & 1;
    const int g = lane >> 2, tig = lane & 3;
    const int m0 = blockIdx.y << 7, n0 = blockIdx.x << 6;
    const float* Ab = A + (size_t)m0 * K;
    const float* Bb = Bm + (size_t)n0 * K;

    float acc[2][4][4];
#pragma unroll
    for (int mt = 0; mt < 2; mt++)
#pragma unroll
        for (int nt = 0; nt < 4; nt++)
#pragma unroll
            for (int c = 0; c < 4; c++) acc[mt][nt][c] = 0.0f;

    float ra[16], rb[8];
    g2_ldg(Ab, Bb, K, 0, tid, ra, rb);
    g2_sts(Apk, Bpk, tid, ra, rb);
    __syncthreads();

    const int NT = K >> 5;
    for (int it = 0; it < NT; it++) {
        if (it + 1 < NT) g2_ldg(Ab, Bb, K, (it + 1) << 5, tid, ra, rb);

        const float* Ac = Apk + (it & 1) * TA_F;
        const float* Bc = Bpk + (it & 1) * TB_F;
#pragma unroll
        for (int kk = 0; kk < 4; kk++) {
            unsigned a[2][4];
#pragma unroll
            for (int mt = 0; mt < 2; mt++) {
                int idx4 = (((wm * 2 + mt) * 4 + kk) * 8 + g) * 4 + (tig ^ kk);
                float4 af = *(const float4*)&Ac[idx4 * 4];
                a[mt][0] = __float_as_uint(af.x);
                a[mt][1] = __float_as_uint(af.y);
                a[mt][2] = __float_as_uint(af.z);
                a[mt][3] = __float_as_uint(af.w);
            }
            unsigned bfr[4][2];
#pragma unroll
            for (int nt = 0; nt < 4; nt++) {
                int idx2 = (((wn * 4 + nt) * 4 + kk) * 8 + g) * 4 + (tig ^ kk);
                float2 bf = *(const float2*)&Bc[idx2 * 2];
                bfr[nt][0] = __float_as_uint(bf.x);
                bfr[nt][1] = __float_as_uint(bf.y);
            }
#pragma unroll
            for (int nt = 0; nt < 4; nt++)
#pragma unroll
                for (int mt = 0; mt < 2; mt++) {
                    asm volatile(
                        "mma.sync.aligned.m16n8k8.row.col.f32.tf32.tf32.f32 "
                        "{%0,%1,%2,%3}, {%4,%5,%6,%7}, {%8,%9}, {%0,%1,%2,%3};"
                        : "+f"(acc[mt][nt][0]), "+f"(acc[mt][nt][1]),
                          "+f"(acc[mt][nt][2]), "+f"(acc[mt][nt][3])
                        : "r"(a[mt][0]), "r"(a[mt][1]), "r"(a[mt][2]), "r"(a[mt][3]),
                          "r"(bfr[nt][0]), "r"(bfr[nt][1]));
                }
        }

        if (it + 1 < NT) {
            g2_sts(Apk + ((it + 1) & 1) * TA_F,
                   Bpk + ((it + 1) & 1) * TB_F, tid, ra, rb);
            __syncthreads();
        }
    }

#pragma unroll
    for (int mt = 0; mt < 2; mt++)
#pragma unroll
        for (int nt = 0; nt < 4; nt++) {
            int col = n0 + wn * 32 + nt * 8 + tig * 2;
            float b0 = bias[col], b1 = bias[col + 1];
            int row0 = m0 + wm * 32 + mt * 16 + g;
            *(float2*)(C + (size_t)row0 * N + col) =
                make_float2(acc[mt][nt][0] + b0, acc[mt][nt][1] + b1);
            *(float2*)(C + (size_t)(row0 + 8) * N + col) =
                make_float2(acc[mt][nt][2] + b0, acc[mt][nt][3] + b1);
        }
}

// ---------------------------------------------------------------------------
// Fused attention v3: full-K smem tiles; V[0:192] bulk-preloaded into the
// Q/K smem region (overlapped with softmax); stage C has 3 syncs total.
// M-tile 64, 2 CTAs/SM. Smem 108 KB.
// ---------------------------------------------------------------------------
#define QSTR 68
#define PSTRIDE 228
#define MT 64
#define P_F (MT * PSTRIDE)
#define Q_F (MT * QSTR)
#define K_F (128 * QSTR)
#define FUSED_SMEM_FLOATS (P_F + Q_F + K_F)   // 27648 -> 108 KB

__global__ __launch_bounds__(256, 2)
void fused_attn(void) {
    extern __shared__ float sm[];
    float* P  = sm;             // [64][228]
    float* Qs = P + P_F;        // [64][68]
    float* Ks = Qs + Q_F;       // [128][68]
    float* Vf = Qs;             // V buffer alias: [192][68]

    const int tid = threadIdx.x;
    const int lane = tid & 31;
    const int warp = tid >> 5;
    const int wm = warp >> 1, wn = warp & 1;
    const int g = lane >> 2, tig = lane & 3;

    const int m0 = blockIdx.x << 6;
    const int bh = blockIdx.y;
    const int b = bh / NHEADS, h = bh - b * NHEADS;
    const float* qkv = g_qkv + (size_t)b * SEQ * QKV3;
    const int hoff = h * HD;
    const float scale = 0.125f;

    // ===== fill Q [64 x 64] (scaled, tf32) =====
#pragma unroll
    for (int it = 0; it < 4; it++) {
        int idx = tid + it * 256;
        int row = idx >> 4, c4 = (idx & 15) << 2;
        int qi = min(m0 + row, SEQ - 1);
        float4 av = *(const float4*)(qkv + (size_t)qi * QKV3 + hoff + c4);
        *(float4*)&Qs[row * QSTR + c4] =
            make_float4(f2tf32(av.x * scale), f2tf32(av.y * scale),
                        f2tf32(av.z * scale), f2tf32(av.w * scale));
    }

    // ===== Stage A: S = Q*K^T + rel_bias -> P =====
    const float* rbp = g_relbias + (size_t)h * SEQ * SPAD;
#pragma unroll
    for (int n0 = 0; n0 < 256; n0 += 128) {
#pragma unroll
        for (int it = 0; it < 8; it++) {
            int idx = tid + it * 256;
            int row = idx >> 4, c4 = (idx & 15) << 2;
            int kj = min(n0 + row, SEQ - 1);
            float4 bv = *(const float4*)(qkv + (size_t)kj * QKV3 + CDIM + hoff + c4);
            *(float4*)&Ks[row * QSTR + c4] =
                make_float4(f2tf32(bv.x), f2tf32(bv.y), f2tf32(bv.z), f2tf32(bv.w));
        }
        __syncthreads();

        float acc[8][4];
#pragma unroll
        for (int nt = 0; nt < 8; nt++)
#pragma unroll
            for (int c = 0; c < 4; c++) acc[nt][c] = 0.0f;

#pragma unroll
        for (int kk = 0; kk < 8; kk++) {
            const int kb = kk * 8;
            unsigned a[4];
            {
                const float* ar0 = &Qs[(wm * 16 + g) * QSTR + kb];
                const float* ar1 = &Qs[(wm * 16 + g + 8) * QSTR + kb];
                a[0] = __float_as_uint(ar0[tig]);
                a[1] = __float_as_uint(ar1[tig]);
                a[2] = __float_as_uint(ar0[tig + 4]);
                a[3] = __float_as_uint(ar1[tig + 4]);
            }
            unsigned bfr[8][2];
#pragma unroll
            for (int nt = 0; nt < 8; nt++) {
                const float* br = &Ks[(wn * 64 + nt * 8 + g) * QSTR + kb];
                bfr[nt][0] = __float_as_uint(br[tig]);
                bfr[nt][1] = __float_as_uint(br[tig + 4]);
            }
#pragma unroll
            for (int nt = 0; nt < 8; nt++) {
                asm volatile(
                    "mma.sync.aligned.m16n8k8.row.col.f32.tf32.tf32.f32 "
                    "{%0,%1,%2,%3}, {%4,%5,%6,%7}, {%8,%9}, {%0,%1,%2,%3};"
                    : "+f"(acc[nt][0]), "+f"(acc[nt][1]),
                      "+f"(acc[nt][2]), "+f"(acc[nt][3])
                    : "r"(a[0]), "r"(a[1]), "r"(a[2]), "r"(a[3]),
                      "r"(bfr[nt][0]), "r"(bfr[nt][1]));
            }
        }

#pragma unroll
        for (int nt = 0; nt < 8; nt++) {
            int col = n0 + wn * 64 + nt * 8 + tig * 2;
            if (col >= SPAD) continue;
#pragma unroll
            for (int half = 0; half < 2; half++) {
                int rloc = wm * 16 + g + half * 8;
                int grow = min(m0 + rloc, SEQ - 1);
                float2 rv2 = *(const float2*)(rbp + (size_t)grow * SPAD + col);
                float p0 = (col < SEQ) ? acc[nt][half * 2 + 0] + rv2.x : -1e30f;
                float p1 = (col + 1 < SEQ) ? acc[nt][half * 2 + 1] + rv2.y : -1e30f;
                *(float2*)&P[rloc * PSTRIDE + col] = make_float2(p0, p1);
            }
        }
        __syncthreads();
    }
    // After this sync: P holds S; Qs/Ks regions free -> become Vf.

    // ===== prefetch V rows 192..223 into registers (for final chunk) =====
    const int vr = tid >> 4;            // 0..15
    const int vc = (tid & 15) << 2;     // 0..60
    float rv[8];
#pragma unroll
    for (int it = 0; it < 2; it++) {
        int j = 192 + vr + it * 16;
        int vj = min(j, SEQ - 1);
        float4 vv = *(const float4*)(qkv + (size_t)vj * QKV3 + 2 * CDIM + hoff + vc);
        rv[it * 4 + 0] = vv.x; rv[it * 4 + 1] = vv.y;
        rv[it * 4 + 2] = vv.z; rv[it * 4 + 3] = vv.w;
    }

    // ===== bulk V fill: rows 0..191 -> Vf (overlaps softmax across warps) =====
#pragma unroll
    for (int it = 0; it < 12; it++) {
        int idx = tid + it * 256;              // 0..3071
        int row = idx >> 4, c4 = (idx & 15) << 2;
        int vj = min(row, SEQ - 1);
        float4 vv = *(const float4*)(qkv + (size_t)vj * QKV3 + 2 * CDIM + hoff + c4);
        *(float4*)&Vf[row * QSTR + c4] =
            make_float4(f2tf32(vv.x), f2tf32(vv.y), f2tf32(vv.z), f2tf32(vv.w));
    }

    // ===== Stage B: softmax (warp per row, 8 rows per warp) =====
    for (int rloc = warp; rloc < MT; rloc += 8) {
        float* pr = P + rloc * PSTRIDE;
        float mx = -1e30f;
        float ev[7];
#pragma unroll
        for (int t = 0; t < 7; t++) {
            ev[t] = pr[lane + t * 32];
            mx = fmaxf(mx, ev[t]);
        }
#pragma unroll
        for (int o = 16; o; o >>= 1) mx = fmaxf(mx, __shfl_xor_sync(0xffffffffu, mx, o));
        float sum = 0.f;
#pragma unroll
        for (int t = 0; t < 7; t++) {
            ev[t] = __expf(ev[t] - mx);
            sum += ev[t];
        }
#pragma unroll
        for (int o = 16; o; o >>= 1) sum += __shfl_xor_sync(0xffffffffu, sum, o);
        float inv = 1.0f / sum;
#pragma unroll
        for (int t = 0; t < 7; t++) pr[lane + t * 32] = f2tf32(ev[t] * inv);
    }
    __syncthreads();   // P normalized AND Vf[0:192] ready

    // ===== Stage C: O = P * V =====
    float acc[4][4];
#pragma unroll
    for (int nt = 0; nt < 4; nt++)
#pragma unroll
        for (int c = 0; c < 4; c++) acc[nt][c] = 0.0f;

#pragma unroll 2
    for (int ch = 0; ch < 7; ch++) {
        const int k0 = ch * 32;
        const float* Vb;
        if (ch < 6) {
            Vb = Vf + k0 * QSTR;
        } else {
            // final chunk: rows 192..223 staged into Vf rows 0..31
            __syncthreads();   // chunks 0..5 fully consumed
#pragma unroll
            for (int it = 0; it < 2; it++) {
                int j = vr + it * 16;
                *(float4*)&Vf[j * QSTR + vc] =
                    make_float4(f2tf32(rv[it * 4 + 0]), f2tf32(rv[it * 4 + 1]),
                                f2tf32(rv[it * 4 + 2]), f2tf32(rv[it * 4 + 3]));
            }
            __syncthreads();
            Vb = Vf;
        }
#pragma unroll
        for (int kk = 0; kk < 4; kk++) {
            const int kb = kk * 8;
            unsigned a[4];
            {
                const float* ar0 = &P[(wm * 16 + g) * PSTRIDE + k0 + kb];
                const float* ar1 = &P[(wm * 16 + g + 8) * PSTRIDE + k0 + kb];
                a[0] = __float_as_uint(ar0[tig]);
                a[1] = __float_as_uint(ar1[tig]);
                a[2] = __float_as_uint(ar0[tig + 4]);
                a[3] = __float_as_uint(ar1[tig + 4]);
            }
            unsigned bfr[4][2];
#pragma unroll
            for (int nt = 0; nt < 4; nt++) {
                int n = wn * 32 + nt * 8 + g;
                bfr[nt][0] = __float_as_uint(Vb[(kb + tig) * QSTR + n]);
                bfr[nt][1] = __float_as_uint(Vb[(kb + tig + 4) * QSTR + n]);
            }
#pragma unroll
            for (int nt = 0; nt < 4; nt++) {
                asm volatile(
                    "mma.sync.aligned.m16n8k8.row.col.f32.tf32.tf32.f32 "
                    "{%0,%1,%2,%3}, {%4,%5,%6,%7}, {%8,%9}, {%0,%1,%2,%3};"
                    : "+f"(acc[nt][0]), "+f"(acc[nt][1]),
                      "+f"(acc[nt][2]), "+f"(acc[nt][3])
                    : "r"(a[0]), "r"(a[1]), "r"(a[2]), "r"(a[3]),
                      "r"(bfr[nt][0]), "r"(bfr[nt][1]));
            }
        }
    }

#pragma unroll
    for (int nt = 0; nt < 4; nt++) {
        int col = wn * 32 + nt * 8 + tig * 2;
        int row0 = m0 + wm * 16 + g;
        if (row0 < SEQ)
            *(float2*)(g_attn + ((size_t)b * SEQ + row0) * CDIM + hoff + col) =
                make_float2(acc[nt][0], acc[nt][1]);
        int row1 = row0 + 8;
        if (row1 < SEQ)
            *(float2*)(g_attn + ((size_t)b * SEQ + row1) * CDIM + hoff + col) =
                make_float2(acc[nt][2], acc[nt][3]);
    }
}

// ---------------------------------------------------------------------------
extern "C" void kernel_launch(void* const* d_in, const int* in_sizes, int n_in,
                              void* d_out, int out_size) {
    const float* x      = (const float*)d_in[0];
    const float* qkv_w  = (const float*)d_in[1];
    const float* q_bias = (const float*)d_in[2];
    const float* v_bias = (const float*)d_in[3];
    const float* table  = (const float*)d_in[4];
    const float* proj_w = (const float*)d_in[5];
    const float* proj_b = (const float*)d_in[6];
    const int*   relidx = (const int*)d_in[7];
    float* out = (float*)d_out;

    float *qkv_p, *attn_p, *bias_p;
    cudaGetSymbolAddress((void**)&qkv_p, g_qkv);
    cudaGetSymbolAddress((void**)&attn_p, g_attn);
    cudaGetSymbolAddress((void**)&bias_p, g_bias);

    const size_t gemm_smem = (size_t)GSMEM_F * sizeof(float);             // 48 KB
    const size_t fused_smem = (size_t)FUSED_SMEM_FLOATS * sizeof(float);  // 108 KB
    cudaFuncSetAttribute(gemm_tf32_bias, cudaFuncAttributeMaxDynamicSharedMemorySize,
                         (int)gemm_smem);
    cudaFuncSetAttribute(fused_attn, cudaFuncAttributeMaxDynamicSharedMemorySize,
                         (int)fused_smem);

    build_bias_kernel<<<(QKV3 + 255) / 256, 256>>>(q_bias, v_bias);
    build_relbias_kernel<<<(NHEADS * SEQ * SPAD + 255) / 256, 256>>>(table, relidx);

    // qkv = x @ qkv_w^T + bias
    gemm_tf32_bias<<<dim3(QKV3 / 64, MROWS / 128), 256, gemm_smem>>>(
        x, qkv_w, bias_p, qkv_p, MROWS, QKV3, CDIM);

    // fused attention -> g_attn
    fused_attn<<<dim3(4, BH), 256, fused_smem>>>();

    // out = attn @ proj_w^T + proj_b
    gemm_tf32_bias<<<dim3(CDIM / 64, MROWS / 128), 256, gemm_smem>>>(
        attn_p, proj_w, proj_b, out, MROWS, CDIM, CDIM);
}

// round 14
// speedup vs baseline: 1.2150x; 1.2150x over previous
#include <cuda_runtime.h>

#define NHEADS 12
#define SEQ 197
#define CDIM 768
#define HD 64
#define QKV3 2304
#define BATCH 128
#define MROWS (BATCH * SEQ)   // 25216
#define SPAD 224
#define BH (BATCH * NHEADS)   // 1536

// Scratch (device globals: allocation-guard safe)
__device__ float g_qkv[(size_t)BATCH * SEQ * QKV3];
__device__ float g_attn[(size_t)BATCH * SEQ * CDIM];
__device__ float g_relbias[(size_t)NHEADS * SEQ * SPAD];
__device__ float g_bias[QKV3];

// ---------------------------------------------------------------------------
__global__ void build_bias_kernel(const float* __restrict__ qb,
                                  const float* __restrict__ vb) {
    int i = blockIdx.x * blockDim.x + threadIdx.x;
    if (i < QKV3) {
        g_bias[i] = (i < CDIM) ? qb[i] : ((i < 2 * CDIM) ? 0.0f : vb[i - 2 * CDIM]);
    }
}

__global__ void build_relbias_kernel(const float* __restrict__ table,
                                     const int* __restrict__ relidx) {
    int idx = blockIdx.x * blockDim.x + threadIdx.x;
    if (idx >= NHEADS * SEQ * SPAD) return;
    int h = idx / (SEQ * SPAD);
    int rem = idx - h * SEQ * SPAD;
    int i = rem / SPAD;
    int j = rem - i * SPAD;
    g_relbias[idx] = (j < SEQ) ? table[relidx[i * SEQ + j] * NHEADS + h] : 0.0f;
}

__device__ __forceinline__ float f2tf32(float x) {
    unsigned u;
    asm("cvt.rna.tf32.f32 %0, %1;" : "=r"(u) : "f"(x));
    return __uint_as_float(u);
}

// ---------------------------------------------------------------------------
// Packed-fragment TF32 GEMM (R8 version — best known): 128x128x32 tiles.
// ---------------------------------------------------------------------------
#define TILE_A_F 4096
#define TILE_B_F 4096
#define GEMM_SMEM_F (2 * TILE_A_F + 2 * TILE_B_F)   // 64 KB

__device__ __forceinline__ void gemm_ldg(const float* __restrict__ Ab,
                                         const float* __restrict__ Bb,
                                         int K, int k0, int tid,
                                         float* ra, float* rb) {
#pragma unroll
    for (int i = 0; i < 2; i++) {
        int t = tid + i * 256;
        int khalf = t & 1, kblk = (t >> 1) & 3, g = (t >> 3) & 7, mblk = t >> 6;
        int r = mblk * 16 + g;
        int k = k0 + kblk * 8 + khalf * 4;
        float4 v0 = *(const float4*)(Ab + (size_t)r * K + k);
        float4 v1 = *(const float4*)(Ab + (size_t)(r + 8) * K + k);
        ra[i * 8 + 0] = v0.x; ra[i * 8 + 1] = v0.y; ra[i * 8 + 2] = v0.z; ra[i * 8 + 3] = v0.w;
        ra[i * 8 + 4] = v1.x; ra[i * 8 + 5] = v1.y; ra[i * 8 + 6] = v1.z; ra[i * 8 + 7] = v1.w;
        int kb2 = t & 3, n = t >> 2;
        const float* bp = Bb + (size_t)n * K + k0 + kb2 * 8;
        float4 w0 = *(const float4*)(bp);
        float4 w1 = *(const float4*)(bp + 4);
        rb[i * 8 + 0] = w0.x; rb[i * 8 + 1] = w0.y; rb[i * 8 + 2] = w0.z; rb[i * 8 + 3] = w0.w;
        rb[i * 8 + 4] = w1.x; rb[i * 8 + 5] = w1.y; rb[i * 8 + 6] = w1.z; rb[i * 8 + 7] = w1.w;
    }
}

__device__ __forceinline__ void gemm_sts(float* __restrict__ Apk,
                                         float* __restrict__ Bpk,
                                         int tid, const float* ra, const float* rb) {
#pragma unroll
    for (int i = 0; i < 2; i++) {
        int t = tid + i * 256;
        int khalf = t & 1, kblk = (t >> 1) & 3, g = (t >> 3) & 7, mblk = t >> 6;
        int abase = ((mblk * 4 + kblk) * 8 + g) * 4;
#pragma unroll
        for (int e = 0; e < 4; e++) {
            int idx4 = abase + (e ^ kblk);
            *(float2*)&Apk[idx4 * 4 + 2 * khalf] =
                make_float2(f2tf32(ra[i * 8 + e]), f2tf32(ra[i * 8 + 4 + e]));
        }
        int kb2 = t & 3, n = t >> 2;
        int bbase = (((n >> 3) * 4 + kb2) * 8 + (n & 7)) * 4;
#pragma unroll
        for (int e = 0; e < 4; e++) {
            int idx2 = bbase + (e ^ kb2);
            *(float2*)&Bpk[idx2 * 2] =
                make_float2(f2tf32(rb[i * 8 + e]), f2tf32(rb[i * 8 + 4 + e]));
        }
    }
}

__global__ __launch_bounds__(256, 2)
void gemm_tf32_bias(const float* __restrict__ A, const float* __restrict__ Bm,
                    const float* __restrict__ bias, float* __restrict__ C,
                    int M, int N, int K) {
    extern __shared__ float gsm[];
    float* Apk = gsm;
    float* Bpk = gsm + 2 * TILE_A_F;

    const int tid = threadIdx.x;
    const int lane = tid & 31;
    const int warp = tid >> 5;
    const int wm = warp >> 1, wn = warp & 1;
    const int g = lane >> 2, tig = lane & 3;
    const int m0 = blockIdx.y << 7, n0 = blockIdx.x << 7;
    const float* Ab = A + (size_t)m0 * K;
    const float* Bb = Bm + (size_t)n0 * K;

    float acc[2][8][4];
#pragma unroll
    for (int mt = 0; mt < 2; mt++)
#pragma unroll
        for (int nt = 0; nt < 8; nt++)
#pragma unroll
            for (int c = 0; c < 4; c++) acc[mt][nt][c] = 0.0f;

    float ra[16], rb[16];
    gemm_ldg(Ab, Bb, K, 0, tid, ra, rb);
    gemm_sts(Apk, Bpk, tid, ra, rb);
    __syncthreads();

    const int NT = K >> 5;
    for (int it = 0; it < NT; it++) {
        if (it + 1 < NT) gemm_ldg(Ab, Bb, K, (it + 1) << 5, tid, ra, rb);

        const float* Ac = Apk + (it & 1) * TILE_A_F;
        const float* Bc = Bpk + (it & 1) * TILE_B_F;
#pragma unroll
        for (int kk = 0; kk < 4; kk++) {
            unsigned a[2][4];
#pragma unroll
            for (int mt = 0; mt < 2; mt++) {
                int idx4 = (((wm * 2 + mt) * 4 + kk) * 8 + g) * 4 + (tig ^ kk);
                float4 af = *(const float4*)&Ac[idx4 * 4];
                a[mt][0] = __float_as_uint(af.x);
                a[mt][1] = __float_as_uint(af.y);
                a[mt][2] = __float_as_uint(af.z);
                a[mt][3] = __float_as_uint(af.w);
            }
            unsigned bfr[8][2];
#pragma unroll
            for (int nt = 0; nt < 8; nt++) {
                int idx2 = (((wn * 8 + nt) * 4 + kk) * 8 + g) * 4 + (tig ^ kk);
                float2 bf = *(const float2*)&Bc[idx2 * 2];
                bfr[nt][0] = __float_as_uint(bf.x);
                bfr[nt][1] = __float_as_uint(bf.y);
            }
#pragma unroll
            for (int nt = 0; nt < 8; nt++)
#pragma unroll
                for (int mt = 0; mt < 2; mt++) {
                    asm volatile(
                        "mma.sync.aligned.m16n8k8.row.col.f32.tf32.tf32.f32 "
                        "{%0,%1,%2,%3}, {%4,%5,%6,%7}, {%8,%9}, {%0,%1,%2,%3};"
                        : "+f"(acc[mt][nt][0]), "+f"(acc[mt][nt][1]),
                          "+f"(acc[mt][nt][2]), "+f"(acc[mt][nt][3])
                        : "r"(a[mt][0]), "r"(a[mt][1]), "r"(a[mt][2]), "r"(a[mt][3]),
                          "r"(bfr[nt][0]), "r"(bfr[nt][1]));
                }
        }

        if (it + 1 < NT) {
            gemm_sts(Apk + ((it + 1) & 1) * TILE_A_F,
                     Bpk + ((it + 1) & 1) * TILE_B_F, tid, ra, rb);
            __syncthreads();
        }
    }

#pragma unroll
    for (int mt = 0; mt < 2; mt++)
#pragma unroll
        for (int nt = 0; nt < 8; nt++) {
            int col = n0 + wn * 64 + nt * 8 + tig * 2;
            float b0 = bias[col], b1 = bias[col + 1];
            int row0 = m0 + wm * 32 + mt * 16 + g;
            *(float2*)(C + (size_t)row0 * N + col) =
                make_float2(acc[mt][nt][0] + b0, acc[mt][nt][1] + b1);
            *(float2*)(C + (size_t)(row0 + 8) * N + col) =
                make_float2(acc[mt][nt][2] + b0, acc[mt][nt][3] + b1);
        }
}

// ---------------------------------------------------------------------------
// Fused attention v4: 512 threads (16 warps), M-tile 64, smem 108 KB,
// 2 CTAs/SM -> 32 warps/SM. Stage A warp tile 16x32; stage C 16x16.
// ---------------------------------------------------------------------------
#define QSTR 68
#define PSTRIDE 228
#define MT 64
#define P_F (MT * PSTRIDE)
#define Q_F (MT * QSTR)
#define K_F (128 * QSTR)
#define FUSED_SMEM_FLOATS (P_F + Q_F + K_F)   // 27648 -> 108 KB
#define FTHR 512

__global__ __launch_bounds__(FTHR, 2)
void fused_attn(void) {
    extern __shared__ float sm[];
    float* P  = sm;             // [64][228]
    float* Qs = P + P_F;        // [64][68]
    float* Ks = Qs + Q_F;       // [128][68]
    float* Vf = Qs;             // V alias: [192][68]

    const int tid = threadIdx.x;
    const int lane = tid & 31;
    const int warp = tid >> 5;             // 0..15
    const int wm = warp >> 2, wn = warp & 3;   // wm 0..3 (16 rows), wn 0..3
    const int g = lane >> 2, tig = lane & 3;

    const int m0 = blockIdx.x << 6;
    const int bh = blockIdx.y;
    const int b = bh / NHEADS, h = bh - b * NHEADS;
    const float* qkv = g_qkv + (size_t)b * SEQ * QKV3;
    const int hoff = h * HD;
    const float scale = 0.125f;

    // ===== fill Q [64 x 64] (scaled, tf32) =====
#pragma unroll
    for (int it = 0; it < 2; it++) {
        int idx = tid + it * FTHR;             // 0..1023
        int row = idx >> 4, c4 = (idx & 15) << 2;
        int qi = min(m0 + row, SEQ - 1);
        float4 av = *(const float4*)(qkv + (size_t)qi * QKV3 + hoff + c4);
        *(float4*)&Qs[row * QSTR + c4] =
            make_float4(f2tf32(av.x * scale), f2tf32(av.y * scale),
                        f2tf32(av.z * scale), f2tf32(av.w * scale));
    }

    // ===== Stage A: S = Q*K^T + rel_bias -> P =====
    const float* rbp = g_relbias + (size_t)h * SEQ * SPAD;
#pragma unroll
    for (int n0 = 0; n0 < 256; n0 += 128) {
#pragma unroll
        for (int it = 0; it < 4; it++) {
            int idx = tid + it * FTHR;         // 0..2047
            int row = idx >> 4, c4 = (idx & 15) << 2;
            int kj = min(n0 + row, SEQ - 1);
            float4 bv = *(const float4*)(qkv + (size_t)kj * QKV3 + CDIM + hoff + c4);
            *(float4*)&Ks[row * QSTR + c4] =
                make_float4(f2tf32(bv.x), f2tf32(bv.y), f2tf32(bv.z), f2tf32(bv.w));
        }
        __syncthreads();

        float acc[4][4];
#pragma unroll
        for (int nt = 0; nt < 4; nt++)
#pragma unroll
            for (int c = 0; c < 4; c++) acc[nt][c] = 0.0f;

#pragma unroll
        for (int kk = 0; kk < 8; kk++) {
            const int kb = kk * 8;
            unsigned a[4];
            {
                const float* ar0 = &Qs[(wm * 16 + g) * QSTR + kb];
                const float* ar1 = &Qs[(wm * 16 + g + 8) * QSTR + kb];
                a[0] = __float_as_uint(ar0[tig]);
                a[1] = __float_as_uint(ar1[tig]);
                a[2] = __float_as_uint(ar0[tig + 4]);
                a[3] = __float_as_uint(ar1[tig + 4]);
            }
            unsigned bfr[4][2];
#pragma unroll
            for (int nt = 0; nt < 4; nt++) {
                const float* br = &Ks[(wn * 32 + nt * 8 + g) * QSTR + kb];
                bfr[nt][0] = __float_as_uint(br[tig]);
                bfr[nt][1] = __float_as_uint(br[tig + 4]);
            }
#pragma unroll
            for (int nt = 0; nt < 4; nt++) {
                asm volatile(
                    "mma.sync.aligned.m16n8k8.row.col.f32.tf32.tf32.f32 "
                    "{%0,%1,%2,%3}, {%4,%5,%6,%7}, {%8,%9}, {%0,%1,%2,%3};"
                    : "+f"(acc[nt][0]), "+f"(acc[nt][1]),
                      "+f"(acc[nt][2]), "+f"(acc[nt][3])
                    : "r"(a[0]), "r"(a[1]), "r"(a[2]), "r"(a[3]),
                      "r"(bfr[nt][0]), "r"(bfr[nt][1]));
            }
        }

        // epilogue -> P (pads -1e30)
#pragma unroll
        for (int nt = 0; nt < 4; nt++) {
            int col = n0 + wn * 32 + nt * 8 + tig * 2;
            if (col >= SPAD) continue;
#pragma unroll
            for (int half = 0; half < 2; half++) {
                int rloc = wm * 16 + g + half * 8;
                int grow = min(m0 + rloc, SEQ - 1);
                float2 rv2 = *(const float2*)(rbp + (size_t)grow * SPAD + col);
                float p0 = (col < SEQ) ? acc[nt][half * 2 + 0] + rv2.x : -1e30f;
                float p1 = (col + 1 < SEQ) ? acc[nt][half * 2 + 1] + rv2.y : -1e30f;
                *(float2*)&P[rloc * PSTRIDE + col] = make_float2(p0, p1);
            }
        }
        __syncthreads();
    }

    // ===== prefetch V rows 192..223 into registers (1 task/thread) =====
    const int vr = tid >> 4;            // 0..31
    const int vc = (tid & 15) << 2;     // 0..60
    float rv[4];
    {
        int vj = min(192 + vr, SEQ - 1);
        float4 vv = *(const float4*)(qkv + (size_t)vj * QKV3 + 2 * CDIM + hoff + vc);
        rv[0] = vv.x; rv[1] = vv.y; rv[2] = vv.z; rv[3] = vv.w;
    }

    // ===== bulk V fill rows 0..191 -> Vf =====
#pragma unroll
    for (int it = 0; it < 6; it++) {
        int idx = tid + it * FTHR;             // 0..3071
        int row = idx >> 4, c4 = (idx & 15) << 2;
        int vj = min(row, SEQ - 1);
        float4 vv = *(const float4*)(qkv + (size_t)vj * QKV3 + 2 * CDIM + hoff + c4);
        *(float4*)&Vf[row * QSTR + c4] =
            make_float4(f2tf32(vv.x), f2tf32(vv.y), f2tf32(vv.z), f2tf32(vv.w));
    }

    // ===== Stage B: softmax (warp per row, 4 rows per warp) =====
    for (int rloc = warp; rloc < MT; rloc += 16) {
        float* pr = P + rloc * PSTRIDE;
        float mx = -1e30f;
        float ev[7];
#pragma unroll
        for (int t = 0; t < 7; t++) {
            ev[t] = pr[lane + t * 32];
            mx = fmaxf(mx, ev[t]);
        }
#pragma unroll
        for (int o = 16; o; o >>= 1) mx = fmaxf(mx, __shfl_xor_sync(0xffffffffu, mx, o));
        float sum = 0.f;
#pragma unroll
        for (int t = 0; t < 7; t++) {
            ev[t] = __expf(ev[t] - mx);
            sum += ev[t];
        }
#pragma unroll
        for (int o = 16; o; o >>= 1) sum += __shfl_xor_sync(0xffffffffu, sum, o);
        float inv = 1.0f / sum;
#pragma unroll
        for (int t = 0; t < 7; t++) pr[lane + t * 32] = f2tf32(ev[t] * inv);
    }
    __syncthreads();   // P normalized AND Vf[0:192] ready

    // ===== Stage C: O = P * V (warp tile 16x16) =====
    float acc[2][4];
#pragma unroll
    for (int nt = 0; nt < 2; nt++)
#pragma unroll
        for (int c = 0; c < 4; c++) acc[nt][c] = 0.0f;

    for (int ch = 0; ch < 7; ch++) {
        const int k0 = ch * 32;
        const float* Vb;
        if (ch < 6) {
            Vb = Vf + k0 * QSTR;
        } else {
            __syncthreads();   // chunks 0..5 consumed
            *(float4*)&Vf[vr * QSTR + vc] =
                make_float4(f2tf32(rv[0]), f2tf32(rv[1]), f2tf32(rv[2]), f2tf32(rv[3]));
            __syncthreads();
            Vb = Vf;
        }
#pragma unroll
        for (int kk = 0; kk < 4; kk++) {
            const int kb = kk * 8;
            unsigned a[4];
            {
                const float* ar0 = &P[(wm * 16 + g) * PSTRIDE + k0 + kb];
                const float* ar1 = &P[(wm * 16 + g + 8) * PSTRIDE + k0 + kb];
                a[0] = __float_as_uint(ar0[tig]);
                a[1] = __float_as_uint(ar1[tig]);
                a[2] = __float_as_uint(ar0[tig + 4]);
                a[3] = __float_as_uint(ar1[tig + 4]);
            }
            unsigned bfr[2][2];
#pragma unroll
            for (int nt = 0; nt < 2; nt++) {
                int n = wn * 16 + nt * 8 + g;
                bfr[nt][0] = __float_as_uint(Vb[(kb + tig) * QSTR + n]);
                bfr[nt][1] = __float_as_uint(Vb[(kb + tig + 4) * QSTR + n]);
            }
#pragma unroll
            for (int nt = 0; nt < 2; nt++) {
                asm volatile(
                    "mma.sync.aligned.m16n8k8.row.col.f32.tf32.tf32.f32 "
                    "{%0,%1,%2,%3}, {%4,%5,%6,%7}, {%8,%9}, {%0,%1,%2,%3};"
                    : "+f"(acc[nt][0]), "+f"(acc[nt][1]),
                      "+f"(acc[nt][2]), "+f"(acc[nt][3])
                    : "r"(a[0]), "r"(a[1]), "r"(a[2]), "r"(a[3]),
                      "r"(bfr[nt][0]), "r"(bfr[nt][1]));
            }
        }
    }

#pragma unroll
    for (int nt = 0; nt < 2; nt++) {
        int col = wn * 16 + nt * 8 + tig * 2;
        int row0 = m0 + wm * 16 + g;
        if (row0 < SEQ)
            *(float2*)(g_attn + ((size_t)b * SEQ + row0) * CDIM + hoff + col) =
                make_float2(acc[nt][0], acc[nt][1]);
        int row1 = row0 + 8;
        if (row1 < SEQ)
            *(float2*)(g_attn + ((size_t)b * SEQ + row1) * CDIM + hoff + col) =
                make_float2(acc[nt][2], acc[nt][3]);
    }
}

// ---------------------------------------------------------------------------
extern "C" void kernel_launch(void* const* d_in, const int* in_sizes, int n_in,
                              void* d_out, int out_size) {
    const float* x      = (const float*)d_in[0];
    const float* qkv_w  = (const float*)d_in[1];
    const float* q_bias = (const float*)d_in[2];
    const float* v_bias = (const float*)d_in[3];
    const float* table  = (const float*)d_in[4];
    const float* proj_w = (const float*)d_in[5];
    const float* proj_b = (const float*)d_in[6];
    const int*   relidx = (const int*)d_in[7];
    float* out = (float*)d_out;

    float *qkv_p, *attn_p, *bias_p;
    cudaGetSymbolAddress((void**)&qkv_p, g_qkv);
    cudaGetSymbolAddress((void**)&attn_p, g_attn);
    cudaGetSymbolAddress((void**)&bias_p, g_bias);

    const size_t gemm_smem = (size_t)GEMM_SMEM_F * sizeof(float);         // 64 KB
    const size_t fused_smem = (size_t)FUSED_SMEM_FLOATS * sizeof(float);  // 108 KB
    cudaFuncSetAttribute(gemm_tf32_bias, cudaFuncAttributeMaxDynamicSharedMemorySize,
                         (int)gemm_smem);
    cudaFuncSetAttribute(fused_attn, cudaFuncAttributeMaxDynamicSharedMemorySize,
                         (int)fused_smem);

    build_bias_kernel<<<(QKV3 + 255) / 256, 256>>>(q_bias, v_bias);
    build_relbias_kernel<<<(NHEADS * SEQ * SPAD + 255) / 256, 256>>>(table, relidx);

    // qkv = x @ qkv_w^T + bias
    gemm_tf32_bias<<<dim3(QKV3 / 128, MROWS / 128), 256, gemm_smem>>>(
        x, qkv_w, bias_p, qkv_p, MROWS, QKV3, CDIM);

    // fused attention -> g_attn
    fused_attn<<<dim3(4, BH), FTHR, fused_smem>>>();

    // out = attn @ proj_w^T + proj_b
    gemm_tf32_bias<<<dim3(CDIM / 128, MROWS / 128), 256, gemm_smem>>>(
        attn_p, proj_w, proj_b, out, MROWS, CDIM, CDIM);
}

// round 15
// speedup vs baseline: 1.2648x; 1.0410x over previous
#include <cuda_runtime.h>

#define NHEADS 12
#define SEQ 197
#define CDIM 768
#define HD 64
#define QKV3 2304
#define BATCH 128
#define MROWS (BATCH * SEQ)   // 25216
#define SPAD 224
#define BH (BATCH * NHEADS)   // 1536

// Scratch (device globals: allocation-guard safe)
__device__ float g_qkv[(size_t)BATCH * SEQ * QKV3];     // tf32-rounded qkv
__device__ float g_attn[(size_t)BATCH * SEQ * CDIM];    // tf32-rounded attn out
__device__ float g_relbias[(size_t)NHEADS * SEQ * SPAD];
__device__ float g_bias[QKV3];
__device__ float g_xr[(size_t)MROWS * CDIM];            // tf32-rounded x
__device__ float g_wr[(size_t)QKV3 * CDIM];             // tf32-rounded qkv_w
__device__ float g_pwr[(size_t)CDIM * CDIM];            // tf32-rounded proj_w

// ---------------------------------------------------------------------------
__global__ void build_bias_kernel(const float* __restrict__ qb,
                                  const float* __restrict__ vb) {
    int i = blockIdx.x * blockDim.x + threadIdx.x;
    if (i < QKV3) {
        g_bias[i] = (i < CDIM) ? qb[i] : ((i < 2 * CDIM) ? 0.0f : vb[i - 2 * CDIM]);
    }
}

__global__ void build_relbias_kernel(const float* __restrict__ table,
                                     const int* __restrict__ relidx) {
    int idx = blockIdx.x * blockDim.x + threadIdx.x;
    if (idx >= NHEADS * SEQ * SPAD) return;
    int h = idx / (SEQ * SPAD);
    int rem = idx - h * SEQ * SPAD;
    int i = rem / SPAD;
    int j = rem - i * SPAD;
    g_relbias[idx] = (j < SEQ) ? table[relidx[i * SEQ + j] * NHEADS + h] : 0.0f;
}

__device__ __forceinline__ float f2tf32(float x) {
    unsigned u;
    asm("cvt.rna.tf32.f32 %0, %1;" : "=r"(u) : "f"(x));
    return __uint_as_float(u);
}

// one-time tf32 rounding pass (float4 vectorized; n % 4 == 0)
__global__ void round_tf32_kernel(const float* __restrict__ in,
                                  float* __restrict__ out, int n4) {
    int i = blockIdx.x * blockDim.x + threadIdx.x;
    if (i < n4) {
        float4 v = ((const float4*)in)[i];
        ((float4*)out)[i] = make_float4(f2tf32(v.x), f2tf32(v.y),
                                        f2tf32(v.z), f2tf32(v.w));
    }
}

// ---------------------------------------------------------------------------
// Packed-fragment TF32 GEMM (R8 layout); inputs pre-rounded -> no cvt in fill.
// round_out=1: epilogue rounds (acc+bias) to tf32 before store.
// ---------------------------------------------------------------------------
#define TILE_A_F 4096
#define TILE_B_F 4096
#define GEMM_SMEM_F (2 * TILE_A_F + 2 * TILE_B_F)   // 64 KB

__device__ __forceinline__ void gemm_ldg(const float* __restrict__ Ab,
                                         const float* __restrict__ Bb,
                                         int K, int k0, int tid,
                                         float* ra, float* rb) {
#pragma unroll
    for (int i = 0; i < 2; i++) {
        int t = tid + i * 256;
        int khalf = t & 1, kblk = (t >> 1) & 3, g = (t >> 3) & 7, mblk = t >> 6;
        int r = mblk * 16 + g;
        int k = k0 + kblk * 8 + khalf * 4;
        float4 v0 = *(const float4*)(Ab + (size_t)r * K + k);
        float4 v1 = *(const float4*)(Ab + (size_t)(r + 8) * K + k);
        ra[i * 8 + 0] = v0.x; ra[i * 8 + 1] = v0.y; ra[i * 8 + 2] = v0.z; ra[i * 8 + 3] = v0.w;
        ra[i * 8 + 4] = v1.x; ra[i * 8 + 5] = v1.y; ra[i * 8 + 6] = v1.z; ra[i * 8 + 7] = v1.w;
        int kb2 = t & 3, n = t >> 2;
        const float* bp = Bb + (size_t)n * K + k0 + kb2 * 8;
        float4 w0 = *(const float4*)(bp);
        float4 w1 = *(const float4*)(bp + 4);
        rb[i * 8 + 0] = w0.x; rb[i * 8 + 1] = w0.y; rb[i * 8 + 2] = w0.z; rb[i * 8 + 3] = w0.w;
        rb[i * 8 + 4] = w1.x; rb[i * 8 + 5] = w1.y; rb[i * 8 + 6] = w1.z; rb[i * 8 + 7] = w1.w;
    }
}

__device__ __forceinline__ void gemm_sts(float* __restrict__ Apk,
                                         float* __restrict__ Bpk,
                                         int tid, const float* ra, const float* rb) {
#pragma unroll
    for (int i = 0; i < 2; i++) {
        int t = tid + i * 256;
        int khalf = t & 1, kblk = (t >> 1) & 3, g = (t >> 3) & 7, mblk = t >> 6;
        int abase = ((mblk * 4 + kblk) * 8 + g) * 4;
#pragma unroll
        for (int e = 0; e < 4; e++) {
            int idx4 = abase + (e ^ kblk);
            *(float2*)&Apk[idx4 * 4 + 2 * khalf] =
                make_float2(ra[i * 8 + e], ra[i * 8 + 4 + e]);
        }
        int kb2 = t & 3, n = t >> 2;
        int bbase = (((n >> 3) * 4 + kb2) * 8 + (n & 7)) * 4;
#pragma unroll
        for (int e = 0; e < 4; e++) {
            int idx2 = bbase + (e ^ kb2);
            *(float2*)&Bpk[idx2 * 2] =
                make_float2(rb[i * 8 + e], rb[i * 8 + 4 + e]);
        }
    }
}

__global__ __launch_bounds__(256, 2)
void gemm_tf32_bias(const float* __restrict__ A, const float* __restrict__ Bm,
                    const float* __restrict__ bias, float* __restrict__ C,
                    int M, int N, int K, int round_out) {
    extern __shared__ float gsm[];
    float* Apk = gsm;
    float* Bpk = gsm + 2 * TILE_A_F;

    const int tid = threadIdx.x;
    const int lane = tid & 31;
    const int warp = tid >> 5;
    const int wm = warp >> 1, wn = warp & 1;
    const int g = lane >> 2, tig = lane & 3;
    const int m0 = blockIdx.y << 7, n0 = blockIdx.x << 7;
    const float* Ab = A + (size_t)m0 * K;
    const float* Bb = Bm + (size_t)n0 * K;

    float acc[2][8][4];
#pragma unroll
    for (int mt = 0; mt < 2; mt++)
#pragma unroll
        for (int nt = 0; nt < 8; nt++)
#pragma unroll
            for (int c = 0; c < 4; c++) acc[mt][nt][c] = 0.0f;

    float ra[16], rb[16];
    gemm_ldg(Ab, Bb, K, 0, tid, ra, rb);
    gemm_sts(Apk, Bpk, tid, ra, rb);
    __syncthreads();

    const int NT = K >> 5;
    for (int it = 0; it < NT; it++) {
        if (it + 1 < NT) gemm_ldg(Ab, Bb, K, (it + 1) << 5, tid, ra, rb);

        const float* Ac = Apk + (it & 1) * TILE_A_F;
        const float* Bc = Bpk + (it & 1) * TILE_B_F;
#pragma unroll
        for (int kk = 0; kk < 4; kk++) {
            unsigned a[2][4];
#pragma unroll
            for (int mt = 0; mt < 2; mt++) {
                int idx4 = (((wm * 2 + mt) * 4 + kk) * 8 + g) * 4 + (tig ^ kk);
                float4 af = *(const float4*)&Ac[idx4 * 4];
                a[mt][0] = __float_as_uint(af.x);
                a[mt][1] = __float_as_uint(af.y);
                a[mt][2] = __float_as_uint(af.z);
                a[mt][3] = __float_as_uint(af.w);
            }
            unsigned bfr[8][2];
#pragma unroll
            for (int nt = 0; nt < 8; nt++) {
                int idx2 = (((wn * 8 + nt) * 4 + kk) * 8 + g) * 4 + (tig ^ kk);
                float2 bf = *(const float2*)&Bc[idx2 * 2];
                bfr[nt][0] = __float_as_uint(bf.x);
                bfr[nt][1] = __float_as_uint(bf.y);
            }
#pragma unroll
            for (int nt = 0; nt < 8; nt++)
#pragma unroll
                for (int mt = 0; mt < 2; mt++) {
                    asm volatile(
                        "mma.sync.aligned.m16n8k8.row.col.f32.tf32.tf32.f32 "
                        "{%0,%1,%2,%3}, {%4,%5,%6,%7}, {%8,%9}, {%0,%1,%2,%3};"
                        : "+f"(acc[mt][nt][0]), "+f"(acc[mt][nt][1]),
                          "+f"(acc[mt][nt][2]), "+f"(acc[mt][nt][3])
                        : "r"(a[mt][0]), "r"(a[mt][1]), "r"(a[mt][2]), "r"(a[mt][3]),
                          "r"(bfr[nt][0]), "r"(bfr[nt][1]));
                }
        }

        if (it + 1 < NT) {
            gemm_sts(Apk + ((it + 1) & 1) * TILE_A_F,
                     Bpk + ((it + 1) & 1) * TILE_B_F, tid, ra, rb);
            __syncthreads();
        }
    }

#pragma unroll
    for (int mt = 0; mt < 2; mt++)
#pragma unroll
        for (int nt = 0; nt < 8; nt++) {
            int col = n0 + wn * 64 + nt * 8 + tig * 2;
            float b0 = bias[col], b1 = bias[col + 1];
            int row0 = m0 + wm * 32 + mt * 16 + g;
            float o00 = acc[mt][nt][0] + b0, o01 = acc[mt][nt][1] + b1;
            float o10 = acc[mt][nt][2] + b0, o11 = acc[mt][nt][3] + b1;
            if (round_out) {
                o00 = f2tf32(o00); o01 = f2tf32(o01);
                o10 = f2tf32(o10); o11 = f2tf32(o11);
            }
            *(float2*)(C + (size_t)row0 * N + col) = make_float2(o00, o01);
            *(float2*)(C + (size_t)(row0 + 8) * N + col) = make_float2(o10, o11);
        }
}

// ---------------------------------------------------------------------------
// Fused attention: 512 threads, M-tile 64, smem 108 KB, 2 CTAs/SM.
// g_qkv is pre-rounded tf32 -> fills are plain copies (Q scaled by 2^-3).
// ---------------------------------------------------------------------------
#define QSTR 68
#define PSTRIDE 228
#define MT 64
#define P_F (MT * PSTRIDE)
#define Q_F (MT * QSTR)
#define K_F (128 * QSTR)
#define FUSED_SMEM_FLOATS (P_F + Q_F + K_F)   // 27648 -> 108 KB
#define FTHR 512

__global__ __launch_bounds__(FTHR, 2)
void fused_attn(void) {
    extern __shared__ float sm[];
    float* P  = sm;             // [64][228]
    float* Qs = P + P_F;        // [64][68]
    float* Ks = Qs + Q_F;       // [128][68]
    float* Vf = Qs;             // V alias: [192][68]

    const int tid = threadIdx.x;
    const int lane = tid & 31;
    const int warp = tid >> 5;                 // 0..15
    const int wm = warp >> 2, wn = warp & 3;
    const int g = lane >> 2, tig = lane & 3;

    const int m0 = blockIdx.x << 6;
    const int bh = blockIdx.y;
    const int b = bh / NHEADS, h = bh - b * NHEADS;
    const float* qkv = g_qkv + (size_t)b * SEQ * QKV3;
    const int hoff = h * HD;
    const float scale = 0.125f;   // 2^-3: exact on tf32 values

    // ===== fill Q (pre-rounded; scale is exact) =====
#pragma unroll
    for (int it = 0; it < 2; it++) {
        int idx = tid + it * FTHR;
        int row = idx >> 4, c4 = (idx & 15) << 2;
        int qi = min(m0 + row, SEQ - 1);
        float4 av = *(const float4*)(qkv + (size_t)qi * QKV3 + hoff + c4);
        *(float4*)&Qs[row * QSTR + c4] =
            make_float4(av.x * scale, av.y * scale, av.z * scale, av.w * scale);
    }

    // ===== Stage A: S = Q*K^T + rel_bias -> P =====
    const float* rbp = g_relbias + (size_t)h * SEQ * SPAD;
#pragma unroll
    for (int n0 = 0; n0 < 256; n0 += 128) {
#pragma unroll
        for (int it = 0; it < 4; it++) {
            int idx = tid + it * FTHR;
            int row = idx >> 4, c4 = (idx & 15) << 2;
            int kj = min(n0 + row, SEQ - 1);
            *(float4*)&Ks[row * QSTR + c4] =
                *(const float4*)(qkv + (size_t)kj * QKV3 + CDIM + hoff + c4);
        }
        __syncthreads();

        float acc[4][4];
#pragma unroll
        for (int nt = 0; nt < 4; nt++)
#pragma unroll
            for (int c = 0; c < 4; c++) acc[nt][c] = 0.0f;

#pragma unroll
        for (int kk = 0; kk < 8; kk++) {
            const int kb = kk * 8;
            unsigned a[4];
            {
                const float* ar0 = &Qs[(wm * 16 + g) * QSTR + kb];
                const float* ar1 = &Qs[(wm * 16 + g + 8) * QSTR + kb];
                a[0] = __float_as_uint(ar0[tig]);
                a[1] = __float_as_uint(ar1[tig]);
                a[2] = __float_as_uint(ar0[tig + 4]);
                a[3] = __float_as_uint(ar1[tig + 4]);
            }
            unsigned bfr[4][2];
#pragma unroll
            for (int nt = 0; nt < 4; nt++) {
                const float* br = &Ks[(wn * 32 + nt * 8 + g) * QSTR + kb];
                bfr[nt][0] = __float_as_uint(br[tig]);
                bfr[nt][1] = __float_as_uint(br[tig + 4]);
            }
#pragma unroll
            for (int nt = 0; nt < 4; nt++) {
                asm volatile(
                    "mma.sync.aligned.m16n8k8.row.col.f32.tf32.tf32.f32 "
                    "{%0,%1,%2,%3}, {%4,%5,%6,%7}, {%8,%9}, {%0,%1,%2,%3};"
                    : "+f"(acc[nt][0]), "+f"(acc[nt][1]),
                      "+f"(acc[nt][2]), "+f"(acc[nt][3])
                    : "r"(a[0]), "r"(a[1]), "r"(a[2]), "r"(a[3]),
                      "r"(bfr[nt][0]), "r"(bfr[nt][1]));
            }
        }

#pragma unroll
        for (int nt = 0; nt < 4; nt++) {
            int col = n0 + wn * 32 + nt * 8 + tig * 2;
            if (col >= SPAD) continue;
#pragma unroll
            for (int half = 0; half < 2; half++) {
                int rloc = wm * 16 + g + half * 8;
                int grow = min(m0 + rloc, SEQ - 1);
                float2 rv2 = *(const float2*)(rbp + (size_t)grow * SPAD + col);
                float p0 = (col < SEQ) ? acc[nt][half * 2 + 0] + rv2.x : -1e30f;
                float p1 = (col + 1 < SEQ) ? acc[nt][half * 2 + 1] + rv2.y : -1e30f;
                *(float2*)&P[rloc * PSTRIDE + col] = make_float2(p0, p1);
            }
        }
        __syncthreads();
    }

    // ===== prefetch V rows 192..223 =====
    const int vr = tid >> 4;
    const int vc = (tid & 15) << 2;
    float rv[4];
    {
        int vj = min(192 + vr, SEQ - 1);
        float4 vv = *(const float4*)(qkv + (size_t)vj * QKV3 + 2 * CDIM + hoff + vc);
        rv[0] = vv.x; rv[1] = vv.y; rv[2] = vv.z; rv[3] = vv.w;
    }

    // ===== bulk V fill rows 0..191 (plain copies) =====
#pragma unroll
    for (int it = 0; it < 6; it++) {
        int idx = tid + it * FTHR;
        int row = idx >> 4, c4 = (idx & 15) << 2;
        int vj = min(row, SEQ - 1);
        *(float4*)&Vf[row * QSTR + c4] =
            *(const float4*)(qkv + (size_t)vj * QKV3 + 2 * CDIM + hoff + c4);
    }

    // ===== Stage B: softmax (rounds P to tf32) =====
    for (int rloc = warp; rloc < MT; rloc += 16) {
        float* pr = P + rloc * PSTRIDE;
        float mx = -1e30f;
        float ev[7];
#pragma unroll
        for (int t = 0; t < 7; t++) {
            ev[t] = pr[lane + t * 32];
            mx = fmaxf(mx, ev[t]);
        }
#pragma unroll
        for (int o = 16; o; o >>= 1) mx = fmaxf(mx, __shfl_xor_sync(0xffffffffu, mx, o));
        float sum = 0.f;
#pragma unroll
        for (int t = 0; t < 7; t++) {
            ev[t] = __expf(ev[t] - mx);
            sum += ev[t];
        }
#pragma unroll
        for (int o = 16; o; o >>= 1) sum += __shfl_xor_sync(0xffffffffu, sum, o);
        float inv = 1.0f / sum;
#pragma unroll
        for (int t = 0; t < 7; t++) pr[lane + t * 32] = f2tf32(ev[t] * inv);
    }
    __syncthreads();

    // ===== Stage C: O = P * V =====
    float acc[2][4];
#pragma unroll
    for (int nt = 0; nt < 2; nt++)
#pragma unroll
        for (int c = 0; c < 4; c++) acc[nt][c] = 0.0f;

    for (int ch = 0; ch < 7; ch++) {
        const int k0 = ch * 32;
        const float* Vb;
        if (ch < 6) {
            Vb = Vf + k0 * QSTR;
        } else {
            __syncthreads();
            *(float4*)&Vf[vr * QSTR + vc] = make_float4(rv[0], rv[1], rv[2], rv[3]);
            __syncthreads();
            Vb = Vf;
        }
#pragma unroll
        for (int kk = 0; kk < 4; kk++) {
            const int kb = kk * 8;
            unsigned a[4];
            {
                const float* ar0 = &P[(wm * 16 + g) * PSTRIDE + k0 + kb];
                const float* ar1 = &P[(wm * 16 + g + 8) * PSTRIDE + k0 + kb];
                a[0] = __float_as_uint(ar0[tig]);
                a[1] = __float_as_uint(ar1[tig]);
                a[2] = __float_as_uint(ar0[tig + 4]);
                a[3] = __float_as_uint(ar1[tig + 4]);
            }
            unsigned bfr[2][2];
#pragma unroll
            for (int nt = 0; nt < 2; nt++) {
                int n = wn * 16 + nt * 8 + g;
                bfr[nt][0] = __float_as_uint(Vb[(kb + tig) * QSTR + n]);
                bfr[nt][1] = __float_as_uint(Vb[(kb + tig + 4) * QSTR + n]);
            }
#pragma unroll
            for (int nt = 0; nt < 2; nt++) {
                asm volatile(
                    "mma.sync.aligned.m16n8k8.row.col.f32.tf32.tf32.f32 "
                    "{%0,%1,%2,%3}, {%4,%5,%6,%7}, {%8,%9}, {%0,%1,%2,%3};"
                    : "+f"(acc[nt][0]), "+f"(acc[nt][1]),
                      "+f"(acc[nt][2]), "+f"(acc[nt][3])
                    : "r"(a[0]), "r"(a[1]), "r"(a[2]), "r"(a[3]),
                      "r"(bfr[nt][0]), "r"(bfr[nt][1]));
            }
        }
    }

    // write g_attn tf32-rounded (feeds proj GEMM)
#pragma unroll
    for (int nt = 0; nt < 2; nt++) {
        int col = wn * 16 + nt * 8 + tig * 2;
        int row0 = m0 + wm * 16 + g;
        if (row0 < SEQ)
            *(float2*)(g_attn + ((size_t)b * SEQ + row0) * CDIM + hoff + col) =
                make_float2(f2tf32(acc[nt][0]), f2tf32(acc[nt][1]));
        int row1 = row0 + 8;
        if (row1 < SEQ)
            *(float2*)(g_attn + ((size_t)b * SEQ + row1) * CDIM + hoff + col) =
                make_float2(f2tf32(acc[nt][2]), f2tf32(acc[nt][3]));
    }
}

// ---------------------------------------------------------------------------
extern "C" void kernel_launch(void* const* d_in, const int* in_sizes, int n_in,
                              void* d_out, int out_size) {
    const float* x      = (const float*)d_in[0];
    const float* qkv_w  = (const float*)d_in[1];
    const float* q_bias = (const float*)d_in[2];
    const float* v_bias = (const float*)d_in[3];
    const float* table  = (const float*)d_in[4];
    const float* proj_w = (const float*)d_in[5];
    const float* proj_b = (const float*)d_in[6];
    const int*   relidx = (const int*)d_in[7];
    float* out = (float*)d_out;

    float *qkv_p, *attn_p, *bias_p, *xr_p, *wr_p, *pwr_p;
    cudaGetSymbolAddress((void**)&qkv_p, g_qkv);
    cudaGetSymbolAddress((void**)&attn_p, g_attn);
    cudaGetSymbolAddress((void**)&bias_p, g_bias);
    cudaGetSymbolAddress((void**)&xr_p, g_xr);
    cudaGetSymbolAddress((void**)&wr_p, g_wr);
    cudaGetSymbolAddress((void**)&pwr_p, g_pwr);

    const size_t gemm_smem = (size_t)GEMM_SMEM_F * sizeof(float);         // 64 KB
    const size_t fused_smem = (size_t)FUSED_SMEM_FLOATS * sizeof(float);  // 108 KB
    cudaFuncSetAttribute(gemm_tf32_bias, cudaFuncAttributeMaxDynamicSharedMemorySize,
                         (int)gemm_smem);
    cudaFuncSetAttribute(fused_attn, cudaFuncAttributeMaxDynamicSharedMemorySize,
                         (int)fused_smem);

    build_bias_kernel<<<(QKV3 + 255) / 256, 256>>>(q_bias, v_bias);
    build_relbias_kernel<<<(NHEADS * SEQ * SPAD + 255) / 256, 256>>>(table, relidx);

    // one-time tf32 rounding of GEMM inputs
    {
        int n4x = MROWS * CDIM / 4;
        round_tf32_kernel<<<(n4x + 255) / 256, 256>>>(x, xr_p, n4x);
        int n4w = QKV3 * CDIM / 4;
        round_tf32_kernel<<<(n4w + 255) / 256, 256>>>(qkv_w, wr_p, n4w);
        int n4p = CDIM * CDIM / 4;
        round_tf32_kernel<<<(n4p + 255) / 256, 256>>>(proj_w, pwr_p, n4p);
    }

    // qkv = x @ qkv_w^T + bias (outputs rounded to tf32)
    gemm_tf32_bias<<<dim3(QKV3 / 128, MROWS / 128), 256, gemm_smem>>>(
        xr_p, wr_p, bias_p, qkv_p, MROWS, QKV3, CDIM, 1);

    // fused attention -> g_attn (rounded)
    fused_attn<<<dim3(4, BH), FTHR, fused_smem>>>();

    // out = attn @ proj_w^T + proj_b (full fp32 output)
    gemm_tf32_bias<<<dim3(CDIM / 128, MROWS / 128), 256, gemm_smem>>>(
        attn_p, pwr_p, proj_b, out, MROWS, CDIM, CDIM, 0);
}

// round 16
// speedup vs baseline: 1.3039x; 1.0309x over previous
#include <cuda_runtime.h>

#define NHEADS 12
#define SEQ 197
#define CDIM 768
#define HD 64
#define QKV3 2304
#define BATCH 128
#define MROWS (BATCH * SEQ)   // 25216
#define SPAD 224
#define BH (BATCH * NHEADS)   // 1536

// Scratch (device globals: allocation-guard safe)
__device__ float g_qkv[(size_t)BATCH * SEQ * QKV3];     // tf32-rounded qkv
__device__ float g_attn[(size_t)BATCH * SEQ * CDIM];    // tf32-rounded attn out
__device__ float g_relbias[(size_t)NHEADS * SEQ * SPAD];
__device__ float g_bias[QKV3];
__device__ float g_xr[(size_t)MROWS * CDIM];            // tf32-rounded x
__device__ float g_wr[(size_t)QKV3 * CDIM];             // tf32-rounded qkv_w
__device__ float g_pwr[(size_t)CDIM * CDIM];            // tf32-rounded proj_w

// ---------------------------------------------------------------------------
__global__ void build_bias_kernel(const float* __restrict__ qb,
                                  const float* __restrict__ vb) {
    int i = blockIdx.x * blockDim.x + threadIdx.x;
    if (i < QKV3) {
        g_bias[i] = (i < CDIM) ? qb[i] : ((i < 2 * CDIM) ? 0.0f : vb[i - 2 * CDIM]);
    }
}

__global__ void build_relbias_kernel(const float* __restrict__ table,
                                     const int* __restrict__ relidx) {
    int idx = blockIdx.x * blockDim.x + threadIdx.x;
    if (idx >= NHEADS * SEQ * SPAD) return;
    int h = idx / (SEQ * SPAD);
    int rem = idx - h * SEQ * SPAD;
    int i = rem / SPAD;
    int j = rem - i * SPAD;
    g_relbias[idx] = (j < SEQ) ? table[relidx[i * SEQ + j] * NHEADS + h] : 0.0f;
}

__device__ __forceinline__ float f2tf32(float x) {
    unsigned u;
    asm("cvt.rna.tf32.f32 %0, %1;" : "=r"(u) : "f"(x));
    return __uint_as_float(u);
}

__global__ void round_tf32_kernel(const float* __restrict__ in,
                                  float* __restrict__ out, int n4) {
    int i = blockIdx.x * blockDim.x + threadIdx.x;
    if (i < n4) {
        float4 v = ((const float4*)in)[i];
        ((float4*)out)[i] = make_float4(f2tf32(v.x), f2tf32(v.y),
                                        f2tf32(v.z), f2tf32(v.w));
    }
}

// ---------------------------------------------------------------------------
// Packed-fragment TF32 GEMM (unchanged from R15).
// ---------------------------------------------------------------------------
#define TILE_A_F 4096
#define TILE_B_F 4096
#define GEMM_SMEM_F (2 * TILE_A_F + 2 * TILE_B_F)   // 64 KB

__device__ __forceinline__ void gemm_ldg(const float* __restrict__ Ab,
                                         const float* __restrict__ Bb,
                                         int K, int k0, int tid,
                                         float* ra, float* rb) {
#pragma unroll
    for (int i = 0; i < 2; i++) {
        int t = tid + i * 256;
        int khalf = t & 1, kblk = (t >> 1) & 3, g = (t >> 3) & 7, mblk = t >> 6;
        int r = mblk * 16 + g;
        int k = k0 + kblk * 8 + khalf * 4;
        float4 v0 = *(const float4*)(Ab + (size_t)r * K + k);
        float4 v1 = *(const float4*)(Ab + (size_t)(r + 8) * K + k);
        ra[i * 8 + 0] = v0.x; ra[i * 8 + 1] = v0.y; ra[i * 8 + 2] = v0.z; ra[i * 8 + 3] = v0.w;
        ra[i * 8 + 4] = v1.x; ra[i * 8 + 5] = v1.y; ra[i * 8 + 6] = v1.z; ra[i * 8 + 7] = v1.w;
        int kb2 = t & 3, n = t >> 2;
        const float* bp = Bb + (size_t)n * K + k0 + kb2 * 8;
        float4 w0 = *(const float4*)(bp);
        float4 w1 = *(const float4*)(bp + 4);
        rb[i * 8 + 0] = w0.x; rb[i * 8 + 1] = w0.y; rb[i * 8 + 2] = w0.z; rb[i * 8 + 3] = w0.w;
        rb[i * 8 + 4] = w1.x; rb[i * 8 + 5] = w1.y; rb[i * 8 + 6] = w1.z; rb[i * 8 + 7] = w1.w;
    }
}

__device__ __forceinline__ void gemm_sts(float* __restrict__ Apk,
                                         float* __restrict__ Bpk,
                                         int tid, const float* ra, const float* rb) {
#pragma unroll
    for (int i = 0; i < 2; i++) {
        int t = tid + i * 256;
        int khalf = t & 1, kblk = (t >> 1) & 3, g = (t >> 3) & 7, mblk = t >> 6;
        int abase = ((mblk * 4 + kblk) * 8 + g) * 4;
#pragma unroll
        for (int e = 0; e < 4; e++) {
            int idx4 = abase + (e ^ kblk);
            *(float2*)&Apk[idx4 * 4 + 2 * khalf] =
                make_float2(ra[i * 8 + e], ra[i * 8 + 4 + e]);
        }
        int kb2 = t & 3, n = t >> 2;
        int bbase = (((n >> 3) * 4 + kb2) * 8 + (n & 7)) * 4;
#pragma unroll
        for (int e = 0; e < 4; e++) {
            int idx2 = bbase + (e ^ kb2);
            *(float2*)&Bpk[idx2 * 2] =
                make_float2(rb[i * 8 + e], rb[i * 8 + 4 + e]);
        }
    }
}

__global__ __launch_bounds__(256, 2)
void gemm_tf32_bias(const float* __restrict__ A, const float* __restrict__ Bm,
                    const float* __restrict__ bias, float* __restrict__ C,
                    int M, int N, int K, int round_out) {
    extern __shared__ float gsm[];
    float* Apk = gsm;
    float* Bpk = gsm + 2 * TILE_A_F;

    const int tid = threadIdx.x;
    const int lane = tid & 31;
    const int warp = tid >> 5;
    const int wm = warp >> 1, wn = warp & 1;
    const int g = lane >> 2, tig = lane & 3;
    const int m0 = blockIdx.y << 7, n0 = blockIdx.x << 7;
    const float* Ab = A + (size_t)m0 * K;
    const float* Bb = Bm + (size_t)n0 * K;

    float acc[2][8][4];
#pragma unroll
    for (int mt = 0; mt < 2; mt++)
#pragma unroll
        for (int nt = 0; nt < 8; nt++)
#pragma unroll
            for (int c = 0; c < 4; c++) acc[mt][nt][c] = 0.0f;

    float ra[16], rb[16];
    gemm_ldg(Ab, Bb, K, 0, tid, ra, rb);
    gemm_sts(Apk, Bpk, tid, ra, rb);
    __syncthreads();

    const int NT = K >> 5;
    for (int it = 0; it < NT; it++) {
        if (it + 1 < NT) gemm_ldg(Ab, Bb, K, (it + 1) << 5, tid, ra, rb);

        const float* Ac = Apk + (it & 1) * TILE_A_F;
        const float* Bc = Bpk + (it & 1) * TILE_B_F;
#pragma unroll
        for (int kk = 0; kk < 4; kk++) {
            unsigned a[2][4];
#pragma unroll
            for (int mt = 0; mt < 2; mt++) {
                int idx4 = (((wm * 2 + mt) * 4 + kk) * 8 + g) * 4 + (tig ^ kk);
                float4 af = *(const float4*)&Ac[idx4 * 4];
                a[mt][0] = __float_as_uint(af.x);
                a[mt][1] = __float_as_uint(af.y);
                a[mt][2] = __float_as_uint(af.z);
                a[mt][3] = __float_as_uint(af.w);
            }
            unsigned bfr[8][2];
#pragma unroll
            for (int nt = 0; nt < 8; nt++) {
                int idx2 = (((wn * 8 + nt) * 4 + kk) * 8 + g) * 4 + (tig ^ kk);
                float2 bf = *(const float2*)&Bc[idx2 * 2];
                bfr[nt][0] = __float_as_uint(bf.x);
                bfr[nt][1] = __float_as_uint(bf.y);
            }
#pragma unroll
            for (int nt = 0; nt < 8; nt++)
#pragma unroll
                for (int mt = 0; mt < 2; mt++) {
                    asm volatile(
                        "mma.sync.aligned.m16n8k8.row.col.f32.tf32.tf32.f32 "
                        "{%0,%1,%2,%3}, {%4,%5,%6,%7}, {%8,%9}, {%0,%1,%2,%3};"
                        : "+f"(acc[mt][nt][0]), "+f"(acc[mt][nt][1]),
                          "+f"(acc[mt][nt][2]), "+f"(acc[mt][nt][3])
                        : "r"(a[mt][0]), "r"(a[mt][1]), "r"(a[mt][2]), "r"(a[mt][3]),
                          "r"(bfr[nt][0]), "r"(bfr[nt][1]));
                }
        }

        if (it + 1 < NT) {
            gemm_sts(Apk + ((it + 1) & 1) * TILE_A_F,
                     Bpk + ((it + 1) & 1) * TILE_B_F, tid, ra, rb);
            __syncthreads();
        }
    }

#pragma unroll
    for (int mt = 0; mt < 2; mt++)
#pragma unroll
        for (int nt = 0; nt < 8; nt++) {
            int col = n0 + wn * 64 + nt * 8 + tig * 2;
            float b0 = bias[col], b1 = bias[col + 1];
            int row0 = m0 + wm * 32 + mt * 16 + g;
            float o00 = acc[mt][nt][0] + b0, o01 = acc[mt][nt][1] + b1;
            float o10 = acc[mt][nt][2] + b0, o11 = acc[mt][nt][3] + b1;
            if (round_out) {
                o00 = f2tf32(o00); o01 = f2tf32(o01);
                o10 = f2tf32(o10); o11 = f2tf32(o11);
            }
            *(float2*)(C + (size_t)row0 * N + col) = make_float2(o00, o01);
            *(float2*)(C + (size_t)(row0 + 8) * N + col) = make_float2(o10, o11);
        }
}

// ---------------------------------------------------------------------------
// Fused attention v5: 256 threads / 8 warps, mt=2 warp tiles for 2x B/V
// fragment reuse. Stage A warp tile 32x32; stage C 32x16. Smem 108 KB,
// 2 CTAs/SM.
// ---------------------------------------------------------------------------
#define QSTR 68
#define PSTRIDE 228
#define MT 64
#define P_F (MT * PSTRIDE)
#define Q_F (MT * QSTR)
#define K_F (128 * QSTR)
#define FUSED_SMEM_FLOATS (P_F + Q_F + K_F)   // 27648 -> 108 KB

__global__ __launch_bounds__(256, 2)
void fused_attn(void) {
    extern __shared__ float sm[];
    float* P  = sm;             // [64][228]
    float* Qs = P + P_F;        // [64][68]
    float* Ks = Qs + Q_F;       // [128][68]
    float* Vf = Qs;             // V alias: [192][68]

    const int tid = threadIdx.x;
    const int lane = tid & 31;
    const int warp = tid >> 5;             // 0..7
    const int wm = warp >> 2, wn = warp & 3;   // wm 0..1 (32 rows), wn 0..3
    const int g = lane >> 2, tig = lane & 3;

    const int m0 = blockIdx.x << 6;
    const int bh = blockIdx.y;
    const int b = bh / NHEADS, h = bh - b * NHEADS;
    const float* qkv = g_qkv + (size_t)b * SEQ * QKV3;
    const int hoff = h * HD;
    const float scale = 0.125f;   // 2^-3: exact on tf32 values

    // ===== fill Q [64x64] (pre-rounded; scale exact) =====
#pragma unroll
    for (int it = 0; it < 4; it++) {
        int idx = tid + it * 256;
        int row = idx >> 4, c4 = (idx & 15) << 2;
        int qi = min(m0 + row, SEQ - 1);
        float4 av = *(const float4*)(qkv + (size_t)qi * QKV3 + hoff + c4);
        *(float4*)&Qs[row * QSTR + c4] =
            make_float4(av.x * scale, av.y * scale, av.z * scale, av.w * scale);
    }

    // ===== Stage A: S = Q*K^T + rel_bias -> P =====
    const float* rbp = g_relbias + (size_t)h * SEQ * SPAD;
#pragma unroll
    for (int n0 = 0; n0 < 256; n0 += 128) {
#pragma unroll
        for (int it = 0; it < 8; it++) {
            int idx = tid + it * 256;
            int row = idx >> 4, c4 = (idx & 15) << 2;
            int kj = min(n0 + row, SEQ - 1);
            *(float4*)&Ks[row * QSTR + c4] =
                *(const float4*)(qkv + (size_t)kj * QKV3 + CDIM + hoff + c4);
        }
        __syncthreads();

        float acc[2][4][4];
#pragma unroll
        for (int mt = 0; mt < 2; mt++)
#pragma unroll
            for (int nt = 0; nt < 4; nt++)
#pragma unroll
                for (int c = 0; c < 4; c++) acc[mt][nt][c] = 0.0f;

#pragma unroll
        for (int kk = 0; kk < 8; kk++) {
            const int kb = kk * 8;
            unsigned a[2][4];
#pragma unroll
            for (int mt = 0; mt < 2; mt++) {
                const float* ar0 = &Qs[(wm * 32 + mt * 16 + g) * QSTR + kb];
                const float* ar1 = &Qs[(wm * 32 + mt * 16 + g + 8) * QSTR + kb];
                a[mt][0] = __float_as_uint(ar0[tig]);
                a[mt][1] = __float_as_uint(ar1[tig]);
                a[mt][2] = __float_as_uint(ar0[tig + 4]);
                a[mt][3] = __float_as_uint(ar1[tig + 4]);
            }
            unsigned bfr[4][2];
#pragma unroll
            for (int nt = 0; nt < 4; nt++) {
                const float* br = &Ks[(wn * 32 + nt * 8 + g) * QSTR + kb];
                bfr[nt][0] = __float_as_uint(br[tig]);
                bfr[nt][1] = __float_as_uint(br[tig + 4]);
            }
#pragma unroll
            for (int nt = 0; nt < 4; nt++)
#pragma unroll
                for (int mt = 0; mt < 2; mt++) {
                    asm volatile(
                        "mma.sync.aligned.m16n8k8.row.col.f32.tf32.tf32.f32 "
                        "{%0,%1,%2,%3}, {%4,%5,%6,%7}, {%8,%9}, {%0,%1,%2,%3};"
                        : "+f"(acc[mt][nt][0]), "+f"(acc[mt][nt][1]),
                          "+f"(acc[mt][nt][2]), "+f"(acc[mt][nt][3])
                        : "r"(a[mt][0]), "r"(a[mt][1]), "r"(a[mt][2]), "r"(a[mt][3]),
                          "r"(bfr[nt][0]), "r"(bfr[nt][1]));
                }
        }

        // epilogue -> P (pads -1e30)
#pragma unroll
        for (int mt = 0; mt < 2; mt++)
#pragma unroll
            for (int nt = 0; nt < 4; nt++) {
                int col = n0 + wn * 32 + nt * 8 + tig * 2;
                if (col >= SPAD) continue;
#pragma unroll
                for (int half = 0; half < 2; half++) {
                    int rloc = wm * 32 + mt * 16 + g + half * 8;
                    int grow = min(m0 + rloc, SEQ - 1);
                    float2 rv2 = *(const float2*)(rbp + (size_t)grow * SPAD + col);
                    float p0 = (col < SEQ) ? acc[mt][nt][half * 2 + 0] + rv2.x : -1e30f;
                    float p1 = (col + 1 < SEQ) ? acc[mt][nt][half * 2 + 1] + rv2.y : -1e30f;
                    *(float2*)&P[rloc * PSTRIDE + col] = make_float2(p0, p1);
                }
            }
        __syncthreads();
    }

    // ===== prefetch V rows 192..223 (2 tasks/thread) =====
    const int vr = tid >> 4;            // 0..15
    const int vc = (tid & 15) << 2;     // 0..60
    float rv[8];
#pragma unroll
    for (int it = 0; it < 2; it++) {
        int vj = min(192 + vr + it * 16, SEQ - 1);
        float4 vv = *(const float4*)(qkv + (size_t)vj * QKV3 + 2 * CDIM + hoff + vc);
        rv[it * 4 + 0] = vv.x; rv[it * 4 + 1] = vv.y;
        rv[it * 4 + 2] = vv.z; rv[it * 4 + 3] = vv.w;
    }

    // ===== bulk V fill rows 0..191 (plain copies) =====
#pragma unroll
    for (int it = 0; it < 12; it++) {
        int idx = tid + it * 256;
        int row = idx >> 4, c4 = (idx & 15) << 2;
        int vj = min(row, SEQ - 1);
        *(float4*)&Vf[row * QSTR + c4] =
            *(const float4*)(qkv + (size_t)vj * QKV3 + 2 * CDIM + hoff + c4);
    }

    // ===== Stage B: softmax (warp per row, 8 rows per warp) =====
    for (int rloc = warp; rloc < MT; rloc += 8) {
        float* pr = P + rloc * PSTRIDE;
        float mx = -1e30f;
        float ev[7];
#pragma unroll
        for (int t = 0; t < 7; t++) {
            ev[t] = pr[lane + t * 32];
            mx = fmaxf(mx, ev[t]);
        }
#pragma unroll
        for (int o = 16; o; o >>= 1) mx = fmaxf(mx, __shfl_xor_sync(0xffffffffu, mx, o));
        float sum = 0.f;
#pragma unroll
        for (int t = 0; t < 7; t++) {
            ev[t] = __expf(ev[t] - mx);
            sum += ev[t];
        }
#pragma unroll
        for (int o = 16; o; o >>= 1) sum += __shfl_xor_sync(0xffffffffu, sum, o);
        float inv = 1.0f / sum;
#pragma unroll
        for (int t = 0; t < 7; t++) pr[lane + t * 32] = f2tf32(ev[t] * inv);
    }
    __syncthreads();   // P normalized AND Vf[0:192] ready

    // ===== Stage C: O = P * V (warp tile 32x16, mt=2, nt=2) =====
    float acc[2][2][4];
#pragma unroll
    for (int mt = 0; mt < 2; mt++)
#pragma unroll
        for (int nt = 0; nt < 2; nt++)
#pragma unroll
            for (int c = 0; c < 4; c++) acc[mt][nt][c] = 0.0f;

    for (int ch = 0; ch < 7; ch++) {
        const int k0 = ch * 32;
        const float* Vb;
        if (ch < 6) {
            Vb = Vf + k0 * QSTR;
        } else {
            __syncthreads();   // chunks 0..5 consumed
#pragma unroll
            for (int it = 0; it < 2; it++) {
                int j = vr + it * 16;
                *(float4*)&Vf[j * QSTR + vc] =
                    make_float4(rv[it * 4 + 0], rv[it * 4 + 1],
                                rv[it * 4 + 2], rv[it * 4 + 3]);
            }
            __syncthreads();
            Vb = Vf;
        }
#pragma unroll
        for (int kk = 0; kk < 4; kk++) {
            const int kb = kk * 8;
            unsigned a[2][4];
#pragma unroll
            for (int mt = 0; mt < 2; mt++) {
                const float* ar0 = &P[(wm * 32 + mt * 16 + g) * PSTRIDE + k0 + kb];
                const float* ar1 = &P[(wm * 32 + mt * 16 + g + 8) * PSTRIDE + k0 + kb];
                a[mt][0] = __float_as_uint(ar0[tig]);
                a[mt][1] = __float_as_uint(ar1[tig]);
                a[mt][2] = __float_as_uint(ar0[tig + 4]);
                a[mt][3] = __float_as_uint(ar1[tig + 4]);
            }
            unsigned bfr[2][2];
#pragma unroll
            for (int nt = 0; nt < 2; nt++) {
                int n = wn * 16 + nt * 8 + g;
                bfr[nt][0] = __float_as_uint(Vb[(kb + tig) * QSTR + n]);
                bfr[nt][1] = __float_as_uint(Vb[(kb + tig + 4) * QSTR + n]);
            }
#pragma unroll
            for (int nt = 0; nt < 2; nt++)
#pragma unroll
                for (int mt = 0; mt < 2; mt++) {
                    asm volatile(
                        "mma.sync.aligned.m16n8k8.row.col.f32.tf32.tf32.f32 "
                        "{%0,%1,%2,%3}, {%4,%5,%6,%7}, {%8,%9}, {%0,%1,%2,%3};"
                        : "+f"(acc[mt][nt][0]), "+f"(acc[mt][nt][1]),
                          "+f"(acc[mt][nt][2]), "+f"(acc[mt][nt][3])
                        : "r"(a[mt][0]), "r"(a[mt][1]), "r"(a[mt][2]), "r"(a[mt][3]),
                          "r"(bfr[nt][0]), "r"(bfr[nt][1]));
                }
        }
    }

    // write g_attn tf32-rounded (feeds proj GEMM)
#pragma unroll
    for (int mt = 0; mt < 2; mt++)
#pragma unroll
        for (int nt = 0; nt < 2; nt++) {
            int col = wn * 16 + nt * 8 + tig * 2;
            int row0 = m0 + wm * 32 + mt * 16 + g;
            if (row0 < SEQ)
                *(float2*)(g_attn + ((size_t)b * SEQ + row0) * CDIM + hoff + col) =
                    make_float2(f2tf32(acc[mt][nt][0]), f2tf32(acc[mt][nt][1]));
            int row1 = row0 + 8;
            if (row1 < SEQ)
                *(float2*)(g_attn + ((size_t)b * SEQ + row1) * CDIM + hoff + col) =
                    make_float2(f2tf32(acc[mt][nt][2]), f2tf32(acc[mt][nt][3]));
        }
}

// ---------------------------------------------------------------------------
extern "C" void kernel_launch(void* const* d_in, const int* in_sizes, int n_in,
                              void* d_out, int out_size) {
    const float* x      = (const float*)d_in[0];
    const float* qkv_w  = (const float*)d_in[1];
    const float* q_bias = (const float*)d_in[2];
    const float* v_bias = (const float*)d_in[3];
    const float* table  = (const float*)d_in[4];
    const float* proj_w = (const float*)d_in[5];
    const float* proj_b = (const float*)d_in[6];
    const int*   relidx = (const int*)d_in[7];
    float* out = (float*)d_out;

    float *qkv_p, *attn_p, *bias_p, *xr_p, *wr_p, *pwr_p;
    cudaGetSymbolAddress((void**)&qkv_p, g_qkv);
    cudaGetSymbolAddress((void**)&attn_p, g_attn);
    cudaGetSymbolAddress((void**)&bias_p, g_bias);
    cudaGetSymbolAddress((void**)&xr_p, g_xr);
    cudaGetSymbolAddress((void**)&wr_p, g_wr);
    cudaGetSymbolAddress((void**)&pwr_p, g_pwr);

    const size_t gemm_smem = (size_t)GEMM_SMEM_F * sizeof(float);         // 64 KB
    const size_t fused_smem = (size_t)FUSED_SMEM_FLOATS * sizeof(float);  // 108 KB
    cudaFuncSetAttribute(gemm_tf32_bias, cudaFuncAttributeMaxDynamicSharedMemorySize,
                         (int)gemm_smem);
    cudaFuncSetAttribute(fused_attn, cudaFuncAttributeMaxDynamicSharedMemorySize,
                         (int)fused_smem);

    build_bias_kernel<<<(QKV3 + 255) / 256, 256>>>(q_bias, v_bias);
    build_relbias_kernel<<<(NHEADS * SEQ * SPAD + 255) / 256, 256>>>(table, relidx);

    // one-time tf32 rounding of GEMM inputs
    {
        int n4x = MROWS * CDIM / 4;
        round_tf32_kernel<<<(n4x + 255) / 256, 256>>>(x, xr_p, n4x);
        int n4w = QKV3 * CDIM / 4;
        round_tf32_kernel<<<(n4w + 255) / 256, 256>>>(qkv_w, wr_p, n4w);
        int n4p = CDIM * CDIM / 4;
        round_tf32_kernel<<<(n4p + 255) / 256, 256>>>(proj_w, pwr_p, n4p);
    }

    // qkv = x @ qkv_w^T + bias (outputs rounded to tf32)
    gemm_tf32_bias<<<dim3(QKV3 / 128, MROWS / 128), 256, gemm_smem>>>(
        xr_p, wr_p, bias_p, qkv_p, MROWS, QKV3, CDIM, 1);

    // fused attention -> g_attn (rounded)
    fused_attn<<<dim3(4, BH), 256, fused_smem>>>();

    // out = attn @ proj_w^T + proj_b (full fp32 output)
    gemm_tf32_bias<<<dim3(CDIM / 128, MROWS / 128), 256, gemm_smem>>>(
        attn_p, pwr_p, proj_b, out, MROWS, CDIM, CDIM, 0);
}